// round 14
// baseline (speedup 1.0000x reference)
#include <cuda_runtime.h>
#include <cuda_bf16.h>
#include <cfloat>
#include <math.h>

// Problem constants (fixed: B=512, F=512, depth=8)
#define BB 512        // batch
#define FF 512        // features
#define NS 255        // n_splits
#define NN 511        // n_nodes
#define NC 21         // N_CAND
#define TEMP 100.0f
#define GRID 128
#define NTHR 512
#define PCOL 256      // padded col stride for GEMM partials
#define NKC 8         // K-split factor

// permuted viol storage: lane's 16 candidates contiguous (16B-vectorizable)
#define VIDX(i) ((((i) & 31) << 4) | ((i) >> 5))

// Scratch (no cudaMalloc allowed)
__device__ float g_part[NKC * BB * PCOL];   // K-split GEMM partials (4 MB)
__device__ float g_qnode[BB * NN];
__device__ float g_ga[NN * NC];
__device__ float g_agrpi[NN];
__device__ float g_anode[NN];

// ---- sync state (zero-init at module load; self-resetting / monotonic) ----
__device__ unsigned g_bar_cnt;
__device__ volatile unsigned g_bar_phase;
__device__ unsigned g_done;                  // P3 completion counter
__device__ volatile unsigned g_scan_flag;    // monotonic scan-done epoch

__device__ __forceinline__ void grid_sync() {
    __syncthreads();
    if (threadIdx.x == 0) {
        unsigned ph = g_bar_phase;
        __threadfence();
        if (atomicAdd(&g_bar_cnt, 1) == GRID - 1) {
            atomicExch(&g_bar_cnt, 0);
            __threadfence();
            atomicExch((unsigned*)&g_bar_phase, ph + 1);
        } else {
            while (g_bar_phase == ph) { }    // tight poll (L2)
        }
        __threadfence();
    }
    __syncthreads();
}

// ---- ordered-key helpers for float max via integer redux ----
__device__ __forceinline__ unsigned ordk(float x) {
    unsigned b = __float_as_uint(x);
    return (b & 0x80000000u) ? ~b : (b | 0x80000000u);
}
__device__ __forceinline__ float iordk(unsigned k) {
    unsigned b = (k & 0x80000000u) ? (k ^ 0x80000000u) : ~k;
    return __uint_as_float(b);
}

// ---- packed f32x2 helpers (FFMA2 — PTX-only, ptxas never auto-emits) ----
__device__ __forceinline__ unsigned long long dup_f32x2(float a) {
    unsigned long long r;
    asm("mov.b64 %0, {%1, %1};" : "=l"(r) : "f"(a));
    return r;
}
__device__ __forceinline__ void ffma2(unsigned long long& d,
                                      unsigned long long a,
                                      unsigned long long b) {
    asm("fma.rn.f32x2 %0, %1, %2, %0;" : "+l"(d) : "l"(a), "l"(b));
}

// Phase-local shared buffers are mutually dead across phases -> one union.
union SmemU {
    struct { float As[32][65]; float Bs[32][128]; } gemm;  // P1: 24.7 KB
    float sq4[4][NS];                                      // P2:  4.0 KB
    float red[64][88];                                     // P3: 22.5 KB
    float s_ga[NN * NC];                                   // P4: 42.9 KB
};

extern "C" __global__ void __launch_bounds__(NTHR, 1)
fused_kernel(const float* __restrict__ x,
             const float* __restrict__ W,
             const float* __restrict__ bias,
             float* __restrict__ out) {
    __shared__ SmemU u;
    __shared__ float s_agrp[512];
    __shared__ __align__(16) float s_viol[512];
    __shared__ float s_cnt[512];             // float: avoids I2F on scan chain

    int tid = threadIdx.x;

    // ====== P1: K-split GEMM (FFMA2). 64x128 tile, K-chunk 64 ==============
    {
        int kc = blockIdx.x & 7;             // 0..7
        int bx = (blockIdx.x >> 3) & 1;      // 0..1
        int by = blockIdx.x >> 4;            // 0..7
        int row0 = by << 6, col0 = bx << 7, kbase = kc << 6;

        int ty = tid & 15;                   // row lane
        int tx = tid >> 4;                   // col-pair lane 0..31
        unsigned long long acc[4][2];
#pragma unroll
        for (int i = 0; i < 4; i++) { acc[i][0] = 0ull; acc[i][1] = 0ull; }

        int la_kk = tid & 31, la_r = tid >> 5;     // A: 64 rows x 32 kk
        int lb_c  = tid & 127, lb_k = tid >> 7;    // B: 32 kk x 128 cols
        bool bok = (col0 + lb_c) < NS;

        float ra[4], rb[8];
#pragma unroll
        for (int i = 0; i < 4; i++)
            ra[i] = x[(row0 + la_r + (i << 4)) * FF + kbase + la_kk];
#pragma unroll
        for (int j = 0; j < 8; j++)
            rb[j] = bok ? W[(kbase + lb_k + (j << 2)) * NS + col0 + lb_c] : 0.f;

#pragma unroll
        for (int s = 0; s < 2; s++) {
            __syncthreads();
#pragma unroll
            for (int i = 0; i < 4; i++) u.gemm.As[la_kk][la_r + (i << 4)] = ra[i];
#pragma unroll
            for (int j = 0; j < 8; j++) u.gemm.Bs[lb_k + (j << 2)][lb_c] = rb[j];
            __syncthreads();

            if (s == 0) {                    // prefetch subtile 1
                int ks = kbase + 32;
#pragma unroll
                for (int i = 0; i < 4; i++)
                    ra[i] = x[(row0 + la_r + (i << 4)) * FF + ks + la_kk];
#pragma unroll
                for (int j = 0; j < 8; j++)
                    rb[j] = bok ? W[(ks + lb_k + (j << 2)) * NS + col0 + lb_c] : 0.f;
            }

#pragma unroll
            for (int kk = 0; kk < 32; kk++) {
                unsigned long long B0 = *reinterpret_cast<const unsigned long long*>(
                    &u.gemm.Bs[kk][tx << 1]);
                unsigned long long B1 = *reinterpret_cast<const unsigned long long*>(
                    &u.gemm.Bs[kk][(tx << 1) + 64]);
                unsigned long long A0 = dup_f32x2(u.gemm.As[kk][ty]);
                unsigned long long A1 = dup_f32x2(u.gemm.As[kk][ty + 16]);
                unsigned long long A2 = dup_f32x2(u.gemm.As[kk][ty + 32]);
                unsigned long long A3 = dup_f32x2(u.gemm.As[kk][ty + 48]);
                ffma2(acc[0][0], A0, B0); ffma2(acc[0][1], A0, B1);
                ffma2(acc[1][0], A1, B0); ffma2(acc[1][1], A1, B1);
                ffma2(acc[2][0], A2, B0); ffma2(acc[2][1], A2, B1);
                ffma2(acc[3][0], A3, B0); ffma2(acc[3][1], A3, B1);
            }
        }
        float* gp = g_part + kc * (BB * PCOL);
#pragma unroll
        for (int i = 0; i < 4; i++) {
            int r = row0 + ty + (i << 4);
#pragma unroll
            for (int j = 0; j < 2; j++) {
                int c = col0 + (tx << 1) + (j << 6);
                float2 v; *reinterpret_cast<unsigned long long*>(&v) = acc[i][j];
                if (c + 1 < NS) {
                    *reinterpret_cast<float2*>(&gp[r * PCOL + c]) = v;
                } else if (c < NS) {
                    gp[r * PCOL + c] = v.x;
                }
            }
        }
    }
    grid_sync();

    // ====== P2: q_node; 4 batch rows per block processed in parallel =======
    {
        for (int idx = tid; idx < 4 * NS; idx += NTHR) {
            int j = idx / NS;
            int col = idx - j * NS;
            int b = (blockIdx.x << 2) + j;
            int o = b * PCOL + col;
            float s = 0.f;
#pragma unroll
            for (int ch = 0; ch < NKC; ch++) s += g_part[ch * (BB * PCOL) + o];
            u.sq4[j][col] = s + bias[col];
        }
        __syncthreads();
        for (int idx = tid; idx < 4 * NN; idx += NTHR) {
            int j = idx / NN;
            int t = idx - j * NN;
            float v = 1.0f;
            int a = t;
            while (a > 0) {
                int pp = (a - 1) >> 1;
                float s = u.sq4[j][pp];
                v = fminf(v, (a & 1) ? -s : s);  // odd = left child -> -sign
                a = pp;
            }
            g_qnode[((blockIdx.x << 2) + j) * NN + t] = v;
        }
        __syncthreads();
    }
    grid_sync();

    // capture scan-flag epoch BEFORE signaling P3 done (strictly pre-increment)
    unsigned v0 = g_scan_flag;

    // ====== P3: g_a + initial softmax; 4 nodes/block (256 active thr) ======
    {
        int nl = tid & 3;                    // node lane
        int bg = (tid >> 2) & 63;            // batch group 0..63
        bool act = tid < 256;
        int n = (blockIdx.x << 2) + nl;
        bool valid = act && (n < NN);

        float acc[NC];
#pragma unroll
        for (int c = 0; c < NC; c++) acc[c] = 0.f;

        if (act) {
#pragma unroll
            for (int it = 0; it < 8; it++) {
                int b = bg + (it << 6);
                float thr = valid ? (g_qnode[b * NN + n] + 0.5f) : 0.f;
#pragma unroll
                for (int c = 0; c < NC; c++) {
                    float a = 0.05f * (float)c;
                    float d = a - thr;
                    if (a <= thr) acc[c] += d * d;
                }
            }
#pragma unroll
            for (int c = 0; c < NC; c++) u.red[bg][nl * NC + c] = acc[c];
        }
        __syncthreads();

        if (tid < 4 * NC) {                  // 84 column sums (deterministic)
            float s = 0.f;
#pragma unroll
            for (int g2 = 0; g2 < 64; g2++) s += u.red[g2][tid];
            int nn2 = (blockIdx.x << 2) + tid / NC;
            int c = tid % NC;
            if (nn2 < NN) {
                float a = 0.05f * (float)c;
                g_ga[nn2 * NC + c] = 0.5f * a * a + 0.5f * s;
            }
            u.red[0][tid] = s;
        }
        __syncthreads();

        if (tid < 4) {                       // softmax init per node
            int n2 = (blockIdx.x << 2) + tid;
            if (n2 < NN) {
                const float* row = &u.red[0][tid * NC];
                float m = -FLT_MAX;
#pragma unroll
                for (int c = 0; c < NC; c++) {
                    float a = 0.05f * (float)c;
                    float g = 0.5f * a * a + 0.5f * row[c];
                    m = fmaxf(m, -TEMP * g);
                }
                float s = 0.f, w = 0.f;
#pragma unroll
                for (int c = 0; c < NC; c++) {
                    float a = 0.05f * (float)c;
                    float g = 0.5f * a * a + 0.5f * row[c];
                    float e = __expf(-TEMP * g - m);
                    s += e; w += a * e;
                }
                g_agrpi[n2] = w / s;
            }
        }
    }
    __syncthreads();
    if (tid == 0) {
        __threadfence();
        atomicAdd(&g_done, 1);
    }

    // ====== P4: scan (block 0) / relu precompute (other blocks) ============
    if (blockIdx.x == 0) {
        if (tid == 0) {
            while (*(volatile unsigned*)&g_done != GRID) { }   // all P3 done
            atomicExch(&g_done, 0);
            __threadfence();
        }
        __syncthreads();

        for (int i = tid; i < NN * NC; i += NTHR) u.s_ga[i] = g_ga[i];
        for (int i = tid; i < 512; i += NTHR) {
            s_cnt[i] = 0.f;
            s_agrp[i] = (i < NN) ? g_agrpi[i] : 0.f;
        }
        __syncthreads();
        // initial viol (permuted storage): anode = agrp (identity n2g)
        if (tid < NN)
            s_viol[VIDX(tid)] = s_agrp[tid] - ((tid == 0) ? 1.0f : s_agrp[(tid - 1) >> 1]);
        if (tid == NN) s_viol[VIDX(NN)] = -FLT_MAX;   // pad sentinel (slot 511)
        __syncthreads();

        if (tid < 32) {                      // warp 0 runs the loop alone
            int lane = tid;
            const unsigned FULL = 0xffffffffu;
            int  cl = (lane < NC) ? lane : (NC - 1);
            float ac = 0.05f * (float)cl;
            const float* sga = u.s_ga;
            const float4* vp = (const float4*)(s_viol + (lane << 4));
            const float FXS = 33554432.0f;   // 2^25 fixed-point scale

            for (int iter = 0; iter <= NN; ++iter) {
                // per-lane first-argmax: depth-4 tournament, ordered brackets,
                // strict > (later wins only if strictly greater) == first index
                float4 q0 = vp[0], q1 = vp[1], q2 = vp[2], q3 = vp[3];
                float vv[16] = { q0.x, q0.y, q0.z, q0.w, q1.x, q1.y, q1.z, q1.w,
                                 q2.x, q2.y, q2.z, q2.w, q3.x, q3.y, q3.z, q3.w };
                float t8v[8]; int t8i[8];
#pragma unroll
                for (int j = 0; j < 8; j++) {
                    bool w = vv[2 * j + 1] > vv[2 * j];
                    t8v[j] = w ? vv[2 * j + 1] : vv[2 * j];
                    t8i[j] = w ? (2 * j + 1) : (2 * j);
                }
                float t4v[4]; int t4i[4];
#pragma unroll
                for (int j = 0; j < 4; j++) {
                    bool w = t8v[2 * j + 1] > t8v[2 * j];
                    t4v[j] = w ? t8v[2 * j + 1] : t8v[2 * j];
                    t4i[j] = w ? t8i[2 * j + 1] : t8i[2 * j];
                }
                float t2v[2]; int t2i[2];
#pragma unroll
                for (int j = 0; j < 2; j++) {
                    bool w = t4v[2 * j + 1] > t4v[2 * j];
                    t2v[j] = w ? t4v[2 * j + 1] : t4v[2 * j];
                    t2i[j] = w ? t4i[2 * j + 1] : t4i[2 * j];
                }
                bool wf = t2v[1] > t2v[0];
                float bv = wf ? t2v[1] : t2v[0];
                int   bk = wf ? t2i[1] : t2i[0];
                int bidx = lane + (bk << 5);

                unsigned key  = ordk(bv);
                unsigned kmax = __reduce_max_sync(FULL, key);
                int t = __reduce_min_sync(FULL, (key == kmax) ? bidx : 1023);
                float vmax = iordk(kmax);

                if (!(vmax <= 1e-8f && t > 0 && iter < NN)) break;

                int p = (t - 1) >> 1;
                int sib = (t & 1) ? (t + 1) : (t - 1);
                int l1 = 2 * t + 1, r1 = 2 * t + 2;

                // all lanes read cnt[t] (broadcast LDS); store deferred to lane 0
                float cnew = s_cnt[t] + 1.0f;

                // dual softmax: groups t and p
                float g1 = (1.0f - cnew) * sga[t * NC + cl];
                if (l1 < NN) g1 += s_cnt[l1] * sga[l1 * NC + cl];
                if (r1 < NN) g1 += s_cnt[r1] * sga[r1 * NC + cl];
                int l2 = 2 * p + 1, r2 = 2 * p + 2;     // == {t, sib}
                float cl2 = (l2 == t) ? cnew : s_cnt[l2];
                float cr2 = (r2 == t) ? cnew : s_cnt[r2];
                float g2v = (1.0f - s_cnt[p]) * sga[p * NC + cl]
                          + cl2 * sga[l2 * NC + cl]
                          + cr2 * sga[r2 * NC + cl];
                float z1 = -TEMP * g1, z2 = -TEMP * g2v;
                unsigned m1 = __reduce_max_sync(FULL, (lane < NC) ? ordk(z1) : 0u);
                unsigned m2 = __reduce_max_sync(FULL, (lane < NC) ? ordk(z2) : 0u);
                float e1 = (lane < NC) ? __expf(z1 - iordk(m1)) : 0.f;
                float e2 = (lane < NC) ? __expf(z2 - iordk(m2)) : 0.f;
                // deterministic sums via integer redux: e in [0,1], scale 2^25
                // (max element is exp(0)=1 -> S >= 2^25; 21*2^25 < 2^30 no ovf)
                unsigned S1 = __reduce_add_sync(FULL, (unsigned)(e1 * FXS));
                unsigned W1 = __reduce_add_sync(FULL, (unsigned)(ac * e1 * FXS));
                unsigned S2 = __reduce_add_sync(FULL, (unsigned)(e2 * FXS));
                unsigned W2 = __reduce_add_sync(FULL, (unsigned)(ac * e2 * FXS));
                float at  = __fdividef((float)W1, (float)S1);
                float ap_ = __fdividef((float)W2, (float)S2);
                if (lane == 0) { s_agrp[t] = at; s_agrp[p] = ap_; s_cnt[t] = cnew; }

                // viol patch from registers (reads of smem touch only UNCHANGED
                // entries; changed {t,p} agrp and cnt[t] substituted from regs)
                if (lane < 11) {
                    int i;
                    switch (lane) {
                        case 0:  i = t; break;
                        case 1:  i = p; break;
                        case 2:  i = sib; break;
                        case 3:  i = l1; break;
                        case 4:  i = r1; break;
                        case 5:  i = 2 * sib + 1; break;
                        case 6:  i = 2 * sib + 2; break;
                        case 7:  i = 2 * l1 + 1; break;
                        case 8:  i = 2 * l1 + 2; break;
                        case 9:  i = 2 * r1 + 1; break;
                        default: i = 2 * r1 + 2; break;
                    }
                    if (i < NN) {
                        auto agrp_of = [&](int xx) -> float {
                            return (xx == t) ? at : (xx == p) ? ap_ : s_agrp[xx];
                        };
                        auto anode_r = [&](int xx) -> float {
                            if (xx == 0) return agrp_of(0);
                            float fc = (xx == t) ? cnew : s_cnt[xx];
                            return fc * agrp_of((xx - 1) >> 1)
                                 + (1.0f - fc) * agrp_of(xx);
                        };
                        float an = anode_r(i);
                        float ap2 = (i == 0) ? 1.0f : anode_r((i - 1) >> 1);
                        s_viol[VIDX(i)] = an - ap2;
                    }
                }
                __syncwarp(FULL);
            }

            // final a_node from (cnt, agrp)
#pragma unroll
            for (int k = 0; k < 16; ++k) {
                int i = lane + (k << 5);
                if (i < NN) {
                    float an;
                    if (i == 0) an = s_agrp[0];
                    else {
                        float fc = s_cnt[i];
                        an = fc * s_agrp[(i - 1) >> 1] + (1.0f - fc) * s_agrp[i];
                    }
                    g_anode[i] = an;
                }
            }
        }
        __syncthreads();
        if (tid == 0) {
            __threadfence();
            atomicAdd((unsigned*)&g_scan_flag, 1);
        }
    } else {
        // overlap: relu-precompute own slice into out while block 0 scans
        for (int i = blockIdx.x * NTHR + tid; i < BB * NN; i += GRID * NTHR)
            out[i] = fmaxf(g_qnode[i], 0.0f);
    }

    // wait for scan-done flag (one-way release; no full barrier)
    if (tid == 0) {
        while (g_scan_flag == v0) { }
        __threadfence();
    }
    __syncthreads();

    // ====== P5: finish trajectory = clip(q_node, 0, a_node) ================
    if (blockIdx.x == 0) {
        for (int i = tid; i < BB * NN; i += GRID * NTHR) {
            int n = i % NN;
            out[i] = fminf(fmaxf(g_qnode[i], 0.0f), __ldg(&g_anode[n]));
        }
    } else {
        for (int i = blockIdx.x * NTHR + tid; i < BB * NN; i += GRID * NTHR) {
            int n = i % NN;
            out[i] = fminf(out[i], __ldg(&g_anode[n]));
        }
    }
}

// ---------------------------------------------------------------------------
extern "C" void kernel_launch(void* const* d_in, const int* in_sizes, int n_in,
                              void* d_out, int out_size) {
    const float* x = (const float*)d_in[0];
    const float* W = (const float*)d_in[1];
    const float* b = (const float*)d_in[2];
    float* out = (float*)d_out;

    fused_kernel<<<GRID, NTHR>>>(x, W, b, out);
}

// round 15
// speedup vs baseline: 1.1977x; 1.1977x over previous
#include <cuda_runtime.h>
#include <cuda_bf16.h>
#include <cfloat>
#include <math.h>

// Problem constants (fixed: B=512, F=512, depth=8)
#define BB 512        // batch
#define FF 512        // features
#define NS 255        // n_splits
#define NN 511        // n_nodes
#define NC 21         // N_CAND
#define TEMP 100.0f
#define GRID 128
#define NTHR 512
#define PCOL 256      // padded col stride for GEMM partials
#define NKC 8         // K-split factor

// permuted viol storage: lane's 16 candidates contiguous (16B-vectorizable)
#define VIDX(i) ((((i) & 31) << 4) | ((i) >> 5))

// Scratch (no cudaMalloc allowed)
__device__ float g_part[NKC * BB * PCOL];   // K-split GEMM partials (4 MB)
__device__ float g_qnode[BB * NN];
__device__ float g_ga[NN * NC];
__device__ float g_agrpi[NN];
__device__ float g_anode[NN];

// ---- sync state (zero-init at module load; self-resetting / monotonic) ----
__device__ unsigned g_bar_cnt;
__device__ volatile unsigned g_bar_phase;
__device__ unsigned g_done;                  // P3 completion counter
__device__ volatile unsigned g_scan_flag;    // monotonic scan-done epoch

__device__ __forceinline__ void grid_sync() {
    __syncthreads();
    if (threadIdx.x == 0) {
        unsigned ph = g_bar_phase;
        __threadfence();
        if (atomicAdd(&g_bar_cnt, 1) == GRID - 1) {
            atomicExch(&g_bar_cnt, 0);
            __threadfence();
            atomicExch((unsigned*)&g_bar_phase, ph + 1);
        } else {
            while (g_bar_phase == ph) { }    // tight poll (L2)
        }
        __threadfence();
    }
    __syncthreads();
}

// ---- ordered-key helpers for float max via integer redux ----
__device__ __forceinline__ unsigned ordk(float x) {
    unsigned b = __float_as_uint(x);
    return (b & 0x80000000u) ? ~b : (b | 0x80000000u);
}
__device__ __forceinline__ float iordk(unsigned k) {
    unsigned b = (k & 0x80000000u) ? (k ^ 0x80000000u) : ~k;
    return __uint_as_float(b);
}

// ---- packed f32x2 helpers (FFMA2 — PTX-only, ptxas never auto-emits) ----
__device__ __forceinline__ unsigned long long dup_f32x2(float a) {
    unsigned long long r;
    asm("mov.b64 %0, {%1, %1};" : "=l"(r) : "f"(a));
    return r;
}
__device__ __forceinline__ void ffma2(unsigned long long& d,
                                      unsigned long long a,
                                      unsigned long long b) {
    asm("fma.rn.f32x2 %0, %1, %2, %0;" : "+l"(d) : "l"(a), "l"(b));
}

// Phase-local shared buffers are mutually dead across phases -> one union.
union SmemU {
    struct { float As[32][65]; float Bs[32][128]; } gemm;  // P1: 24.7 KB
    struct { float sq4[4][NS]; float sv[4][NN]; } p2;      // P2: 12.3 KB
    float red[64][88];                                     // P3: 22.5 KB
    float s_ga[NN * NC];                                   // P4: 42.9 KB
};

extern "C" __global__ void __launch_bounds__(NTHR, 1)
fused_kernel(const float* __restrict__ x,
             const float* __restrict__ W,
             const float* __restrict__ bias,
             float* __restrict__ out) {
    __shared__ SmemU u;
    __shared__ float s_agrp[512];
    __shared__ __align__(16) float s_viol[512];
    __shared__ float s_cnt[512];             // float: avoids I2F on scan chain

    int tid = threadIdx.x;

    // ====== P1: K-split GEMM (FFMA2). 64x128 tile, K-chunk 64 ==============
    {
        int kc = blockIdx.x & 7;             // 0..7
        int bx = (blockIdx.x >> 3) & 1;      // 0..1
        int by = blockIdx.x >> 4;            // 0..7
        int row0 = by << 6, col0 = bx << 7, kbase = kc << 6;

        int ty = tid & 15;                   // row lane
        int tx = tid >> 4;                   // col-pair lane 0..31
        unsigned long long acc[4][2];
#pragma unroll
        for (int i = 0; i < 4; i++) { acc[i][0] = 0ull; acc[i][1] = 0ull; }

        int la_kk = tid & 31, la_r = tid >> 5;     // A: 64 rows x 32 kk
        int lb_c  = tid & 127, lb_k = tid >> 7;    // B: 32 kk x 128 cols
        bool bok = (col0 + lb_c) < NS;

        float ra[4], rb[8];
#pragma unroll
        for (int i = 0; i < 4; i++)
            ra[i] = x[(row0 + la_r + (i << 4)) * FF + kbase + la_kk];
#pragma unroll
        for (int j = 0; j < 8; j++)
            rb[j] = bok ? W[(kbase + lb_k + (j << 2)) * NS + col0 + lb_c] : 0.f;

#pragma unroll
        for (int s = 0; s < 2; s++) {
            __syncthreads();
#pragma unroll
            for (int i = 0; i < 4; i++) u.gemm.As[la_kk][la_r + (i << 4)] = ra[i];
#pragma unroll
            for (int j = 0; j < 8; j++) u.gemm.Bs[lb_k + (j << 2)][lb_c] = rb[j];
            __syncthreads();

            if (s == 0) {                    // prefetch subtile 1
                int ks = kbase + 32;
#pragma unroll
                for (int i = 0; i < 4; i++)
                    ra[i] = x[(row0 + la_r + (i << 4)) * FF + ks + la_kk];
#pragma unroll
                for (int j = 0; j < 8; j++)
                    rb[j] = bok ? W[(ks + lb_k + (j << 2)) * NS + col0 + lb_c] : 0.f;
            }

#pragma unroll
            for (int kk = 0; kk < 32; kk++) {
                unsigned long long B0 = *reinterpret_cast<const unsigned long long*>(
                    &u.gemm.Bs[kk][tx << 1]);
                unsigned long long B1 = *reinterpret_cast<const unsigned long long*>(
                    &u.gemm.Bs[kk][(tx << 1) + 64]);
                unsigned long long A0 = dup_f32x2(u.gemm.As[kk][ty]);
                unsigned long long A1 = dup_f32x2(u.gemm.As[kk][ty + 16]);
                unsigned long long A2 = dup_f32x2(u.gemm.As[kk][ty + 32]);
                unsigned long long A3 = dup_f32x2(u.gemm.As[kk][ty + 48]);
                ffma2(acc[0][0], A0, B0); ffma2(acc[0][1], A0, B1);
                ffma2(acc[1][0], A1, B0); ffma2(acc[1][1], A1, B1);
                ffma2(acc[2][0], A2, B0); ffma2(acc[2][1], A2, B1);
                ffma2(acc[3][0], A3, B0); ffma2(acc[3][1], A3, B1);
            }
        }
        float* gp = g_part + kc * (BB * PCOL);
#pragma unroll
        for (int i = 0; i < 4; i++) {
            int r = row0 + ty + (i << 4);
#pragma unroll
            for (int j = 0; j < 2; j++) {
                int c = col0 + (tx << 1) + (j << 6);
                float2 v; *reinterpret_cast<unsigned long long*>(&v) = acc[i][j];
                if (c + 1 < NS) {
                    *reinterpret_cast<float2*>(&gp[r * PCOL + c]) = v;
                } else if (c < NS) {
                    gp[r * PCOL + c] = v.x;
                }
            }
        }
    }
    grid_sync();

    // ====== P2: q_node via LEVEL-ORDER recurrence (bit-identical to walk:
    // min over ancestors is order-independent). 4 batch rows per block. =====
    {
        for (int idx = tid; idx < 4 * NS; idx += NTHR) {
            int j = idx / NS;
            int col = idx - j * NS;
            int b = (blockIdx.x << 2) + j;
            int o = b * PCOL + col;
            float s = 0.f;
#pragma unroll
            for (int ch = 0; ch < NKC; ch++) s += g_part[ch * (BB * PCOL) + o];
            u.p2.sq4[j][col] = s + bias[col];
        }
        if (tid < 4) {                       // root: empty ancestor set -> 1
            u.p2.sv[tid][0] = 1.0f;
            g_qnode[((blockIdx.x << 2) + tid) * NN + 0] = 1.0f;
        }
        __syncthreads();

#pragma unroll
        for (int d = 1; d <= 8; d++) {       // level d: nodes [2^d-1, 2^(d+1)-1)
            int start = (1 << d) - 1;
            int cnt = 1 << d;
            for (int idx = tid; idx < 4 * cnt; idx += NTHR) {
                int j = idx >> d;
                int off = idx & (cnt - 1);
                int n = start + off;
                int p = (n - 1) >> 1;        // p <= 254 < NS: valid split
                float s = u.p2.sq4[j][p];
                float v = fminf(u.p2.sv[j][p], (n & 1) ? -s : s);
                u.p2.sv[j][n] = v;
                g_qnode[((blockIdx.x << 2) + j) * NN + n] = v;
            }
            __syncthreads();
        }
    }
    grid_sync();

    // capture scan-flag epoch BEFORE signaling P3 done (strictly pre-increment)
    unsigned v0 = g_scan_flag;

    // ====== P3: g_a + initial softmax; 4 nodes/block (256 active thr) ======
    {
        int nl = tid & 3;                    // node lane
        int bg = (tid >> 2) & 63;            // batch group 0..63
        bool act = tid < 256;
        int n = (blockIdx.x << 2) + nl;
        bool valid = act && (n < NN);

        float acc[NC];
#pragma unroll
        for (int c = 0; c < NC; c++) acc[c] = 0.f;

        if (act) {
#pragma unroll
            for (int it = 0; it < 8; it++) {
                int b = bg + (it << 6);
                float thr = valid ? (g_qnode[b * NN + n] + 0.5f) : 0.f;
#pragma unroll
                for (int c = 0; c < NC; c++) {
                    float a = 0.05f * (float)c;
                    float d = a - thr;
                    if (a <= thr) acc[c] += d * d;
                }
            }
#pragma unroll
            for (int c = 0; c < NC; c++) u.red[bg][nl * NC + c] = acc[c];
        }
        __syncthreads();

        if (tid < 4 * NC) {                  // 84 column sums (deterministic)
            float s = 0.f;
#pragma unroll
            for (int g2 = 0; g2 < 64; g2++) s += u.red[g2][tid];
            int nn2 = (blockIdx.x << 2) + tid / NC;
            int c = tid % NC;
            if (nn2 < NN) {
                float a = 0.05f * (float)c;
                g_ga[nn2 * NC + c] = 0.5f * a * a + 0.5f * s;
            }
            u.red[0][tid] = s;
        }
        __syncthreads();

        if (tid < 4) {                       // softmax init per node
            int n2 = (blockIdx.x << 2) + tid;
            if (n2 < NN) {
                const float* row = &u.red[0][tid * NC];
                float m = -FLT_MAX;
#pragma unroll
                for (int c = 0; c < NC; c++) {
                    float a = 0.05f * (float)c;
                    float g = 0.5f * a * a + 0.5f * row[c];
                    m = fmaxf(m, -TEMP * g);
                }
                float s = 0.f, w = 0.f;
#pragma unroll
                for (int c = 0; c < NC; c++) {
                    float a = 0.05f * (float)c;
                    float g = 0.5f * a * a + 0.5f * row[c];
                    float e = expf(-TEMP * g - m);
                    s += e; w += a * e;
                }
                g_agrpi[n2] = w / s;
            }
        }
    }
    __syncthreads();
    if (tid == 0) {
        __threadfence();
        atomicAdd(&g_done, 1);
    }

    // ====== P4: scan (block 0 only; exact R13 loop) ========================
    if (blockIdx.x == 0) {
        if (tid == 0) {
            while (*(volatile unsigned*)&g_done != GRID) { }   // all P3 done
            atomicExch(&g_done, 0);
            __threadfence();
        }
        __syncthreads();

        for (int i = tid; i < NN * NC; i += NTHR) u.s_ga[i] = g_ga[i];
        for (int i = tid; i < 512; i += NTHR) {
            s_cnt[i] = 0.f;
            s_agrp[i] = (i < NN) ? g_agrpi[i] : 0.f;
        }
        __syncthreads();
        // initial viol (permuted storage): anode = agrp (identity n2g)
        if (tid < NN)
            s_viol[VIDX(tid)] = s_agrp[tid] - ((tid == 0) ? 1.0f : s_agrp[(tid - 1) >> 1]);
        if (tid == NN) s_viol[VIDX(NN)] = -FLT_MAX;   // pad sentinel (slot 511)
        __syncthreads();

        if (tid < 32) {                      // warp 0 runs the loop alone
            int lane = tid;
            const unsigned FULL = 0xffffffffu;
            int  cl = (lane < NC) ? lane : (NC - 1);
            float ac = 0.05f * (float)cl;
            const float* sga = u.s_ga;
            const float4* vp = (const float4*)(s_viol + (lane << 4));

            for (int iter = 0; iter <= NN; ++iter) {
                // per-lane first-argmax over 16 contiguous (permuted) viols
                float4 q0 = vp[0], q1 = vp[1], q2 = vp[2], q3 = vp[3];
                float vv[16] = { q0.x, q0.y, q0.z, q0.w, q1.x, q1.y, q1.z, q1.w,
                                 q2.x, q2.y, q2.z, q2.w, q3.x, q3.y, q3.z, q3.w };
                float bv = vv[0]; int bk = 0;
#pragma unroll
                for (int k = 1; k < 16; k++)
                    if (vv[k] > bv) { bv = vv[k]; bk = k; }   // strict > = first idx
                int bidx = lane + (bk << 5);

                unsigned key  = ordk(bv);
                unsigned kmax = __reduce_max_sync(FULL, key);
                int t = __reduce_min_sync(FULL, (key == kmax) ? bidx : 1023);
                float vmax = iordk(kmax);

                if (!(vmax <= 1e-8f && t > 0 && iter < NN)) break;

                int p = (t - 1) >> 1;
                int sib = (t & 1) ? (t + 1) : (t - 1);
                int l1 = 2 * t + 1, r1 = 2 * t + 2;

                // all lanes read cnt[t] (broadcast LDS); store deferred to lane 0
                float cnew = s_cnt[t] + 1.0f;

                // dual softmax: groups t and p (same association order as before)
                float g1 = (1.0f - cnew) * sga[t * NC + cl];
                if (l1 < NN) g1 += s_cnt[l1] * sga[l1 * NC + cl];
                if (r1 < NN) g1 += s_cnt[r1] * sga[r1 * NC + cl];
                int l2 = 2 * p + 1, r2 = 2 * p + 2;     // == {t, sib}
                float cl2 = (l2 == t) ? cnew : s_cnt[l2];
                float cr2 = (r2 == t) ? cnew : s_cnt[r2];
                float g2v = (1.0f - s_cnt[p]) * sga[p * NC + cl]
                          + cl2 * sga[l2 * NC + cl]
                          + cr2 * sga[r2 * NC + cl];
                float z1 = -TEMP * g1, z2 = -TEMP * g2v;
                unsigned m1 = __reduce_max_sync(FULL, (lane < NC) ? ordk(z1) : 0u);
                unsigned m2 = __reduce_max_sync(FULL, (lane < NC) ? ordk(z2) : 0u);
                float e1 = (lane < NC) ? expf(z1 - iordk(m1)) : 0.f;
                float e2 = (lane < NC) ? expf(z2 - iordk(m2)) : 0.f;
                float s1 = e1, w1 = ac * e1, s2 = e2, w2 = ac * e2;
#pragma unroll
                for (int off = 16; off; off >>= 1) {
                    s1 += __shfl_xor_sync(FULL, s1, off);
                    w1 += __shfl_xor_sync(FULL, w1, off);
                    s2 += __shfl_xor_sync(FULL, s2, off);
                    w2 += __shfl_xor_sync(FULL, w2, off);
                }
                // butterfly leaves identical bits in ALL lanes -> register agrp
                float at  = w1 / s1;
                float ap_ = w2 / s2;
                if (lane == 0) { s_agrp[t] = at; s_agrp[p] = ap_; s_cnt[t] = cnew; }

                // viol patch from registers (reads of smem touch only UNCHANGED
                // entries; changed {t,p} agrp and cnt[t] substituted from regs)
                if (lane < 11) {
                    int i;
                    switch (lane) {
                        case 0:  i = t; break;
                        case 1:  i = p; break;
                        case 2:  i = sib; break;
                        case 3:  i = l1; break;
                        case 4:  i = r1; break;
                        case 5:  i = 2 * sib + 1; break;
                        case 6:  i = 2 * sib + 2; break;
                        case 7:  i = 2 * l1 + 1; break;
                        case 8:  i = 2 * l1 + 2; break;
                        case 9:  i = 2 * r1 + 1; break;
                        default: i = 2 * r1 + 2; break;
                    }
                    if (i < NN) {
                        auto agrp_of = [&](int xx) -> float {
                            return (xx == t) ? at : (xx == p) ? ap_ : s_agrp[xx];
                        };
                        auto anode_r = [&](int xx) -> float {
                            if (xx == 0) return agrp_of(0);
                            float fc = (xx == t) ? cnew : s_cnt[xx];
                            return fc * agrp_of((xx - 1) >> 1)
                                 + (1.0f - fc) * agrp_of(xx);
                        };
                        float an = anode_r(i);
                        float ap2 = (i == 0) ? 1.0f : anode_r((i - 1) >> 1);
                        s_viol[VIDX(i)] = an - ap2;
                    }
                }
                __syncwarp(FULL);
            }

            // final a_node from (cnt, agrp)
#pragma unroll
            for (int k = 0; k < 16; ++k) {
                int i = lane + (k << 5);
                if (i < NN) {
                    float an;
                    if (i == 0) an = s_agrp[0];
                    else {
                        float fc = s_cnt[i];
                        an = fc * s_agrp[(i - 1) >> 1] + (1.0f - fc) * s_agrp[i];
                    }
                    g_anode[i] = an;
                }
            }
        }
        __syncthreads();
        if (tid == 0) {
            __threadfence();
            atomicAdd((unsigned*)&g_scan_flag, 1);
        }
    }

    // wait for scan-done flag (one-way release; no full barrier)
    if (tid == 0) {
        while (g_scan_flag == v0) { }
        __threadfence();
    }
    __syncthreads();

    // ====== P5: trajectory = clip(q_node, 0, a_node); n-indexed, no mod ====
    {
        int b0 = blockIdx.x << 2;
        for (int n = tid; n < NN; n += NTHR) {     // single pass: NN < NTHR
            float an = __ldg(&g_anode[n]);
#pragma unroll
            for (int j = 0; j < 4; j++) {
                int o = (b0 + j) * NN + n;
                out[o] = fminf(fmaxf(g_qnode[o], 0.0f), an);
            }
        }
    }
}

// ---------------------------------------------------------------------------
extern "C" void kernel_launch(void* const* d_in, const int* in_sizes, int n_in,
                              void* d_out, int out_size) {
    const float* x = (const float*)d_in[0];
    const float* W = (const float*)d_in[1];
    const float* b = (const float*)d_in[2];
    float* out = (float*)d_out;

    fused_kernel<<<GRID, NTHR>>>(x, W, b, out);
}

// round 16
// speedup vs baseline: 1.3078x; 1.0920x over previous
#include <cuda_runtime.h>
#include <cuda_bf16.h>
#include <cfloat>
#include <math.h>

// Problem constants (fixed: B=512, F=512, depth=8)
#define BB 512        // batch
#define FF 512        // features
#define NS 255        // n_splits
#define NN 511        // n_nodes
#define NC 21         // N_CAND
#define TEMP 100.0f
#define GRID 128
#define NTHR 512
#define PCOL 256      // padded col stride for GEMM partials
#define NKC 8         // K-split factor

// permuted viol storage: lane's 16 candidates contiguous (16B-vectorizable)
#define VIDX(i) ((((i) & 31) << 4) | ((i) >> 5))

// Scratch (no cudaMalloc allowed)
__device__ float g_part[NKC * BB * PCOL];   // K-split GEMM partials (4 MB)
__device__ float g_qnode[BB * NN];
__device__ float g_ga[NN * NC];
__device__ float g_agrpi[NN];

// ---- sync state (zero-init at module load; self-resetting) ----
__device__ unsigned g_bar_cnt;
__device__ volatile unsigned g_bar_phase;

__device__ __forceinline__ void grid_sync() {
    __syncthreads();
    if (threadIdx.x == 0) {
        unsigned ph = g_bar_phase;
        __threadfence();
        if (atomicAdd(&g_bar_cnt, 1) == GRID - 1) {
            atomicExch(&g_bar_cnt, 0);
            __threadfence();
            atomicExch((unsigned*)&g_bar_phase, ph + 1);
        } else {
            while (g_bar_phase == ph) { }    // tight poll (L2)
        }
        __threadfence();
    }
    __syncthreads();
}

// ---- ordered-key helpers for float max via integer redux ----
__device__ __forceinline__ unsigned ordk(float x) {
    unsigned b = __float_as_uint(x);
    return (b & 0x80000000u) ? ~b : (b | 0x80000000u);
}
__device__ __forceinline__ float iordk(unsigned k) {
    unsigned b = (k & 0x80000000u) ? (k ^ 0x80000000u) : ~k;
    return __uint_as_float(b);
}

// ---- packed f32x2 helpers (FFMA2 — PTX-only, ptxas never auto-emits) ----
__device__ __forceinline__ unsigned long long dup_f32x2(float a) {
    unsigned long long r;
    asm("mov.b64 %0, {%1, %1};" : "=l"(r) : "f"(a));
    return r;
}
__device__ __forceinline__ void ffma2(unsigned long long& d,
                                      unsigned long long a,
                                      unsigned long long b) {
    asm("fma.rn.f32x2 %0, %1, %2, %0;" : "+l"(d) : "l"(a), "l"(b));
}

// Phase-local shared buffers are mutually dead across phases -> one union.
union SmemU {
    struct { float As[32][65]; float Bs[32][128]; } gemm;  // P1: 24.7 KB
    struct { float sq4[4][NS]; float sv[4][NN]; } p2;      // P2: 12.3 KB
    float red[64][88];                                     // P3: 22.5 KB
    float s_ga[NN * NC];                                   // P4: 42.9 KB
};

extern "C" __global__ void __launch_bounds__(NTHR, 1)
fused_kernel(const float* __restrict__ x,
             const float* __restrict__ W,
             const float* __restrict__ bias,
             float* __restrict__ out) {
    __shared__ SmemU u;
    __shared__ float s_agrp[512];
    __shared__ __align__(16) float s_viol[512];
    __shared__ float s_cnt[512];             // float: avoids I2F on scan chain

    int tid = threadIdx.x;

    // ====== P1: K-split GEMM (FFMA2). 64x128 tile, K-chunk 64 ==============
    {
        int kc = blockIdx.x & 7;             // 0..7
        int bx = (blockIdx.x >> 3) & 1;      // 0..1
        int by = blockIdx.x >> 4;            // 0..7
        int row0 = by << 6, col0 = bx << 7, kbase = kc << 6;

        int ty = tid & 15;                   // row lane
        int tx = tid >> 4;                   // col-pair lane 0..31
        unsigned long long acc[4][2];
#pragma unroll
        for (int i = 0; i < 4; i++) { acc[i][0] = 0ull; acc[i][1] = 0ull; }

        int la_kk = tid & 31, la_r = tid >> 5;     // A: 64 rows x 32 kk
        int lb_c  = tid & 127, lb_k = tid >> 7;    // B: 32 kk x 128 cols
        bool bok = (col0 + lb_c) < NS;

        float ra[4], rb[8];
#pragma unroll
        for (int i = 0; i < 4; i++)
            ra[i] = x[(row0 + la_r + (i << 4)) * FF + kbase + la_kk];
#pragma unroll
        for (int j = 0; j < 8; j++)
            rb[j] = bok ? W[(kbase + lb_k + (j << 2)) * NS + col0 + lb_c] : 0.f;

#pragma unroll
        for (int s = 0; s < 2; s++) {
            __syncthreads();
#pragma unroll
            for (int i = 0; i < 4; i++) u.gemm.As[la_kk][la_r + (i << 4)] = ra[i];
#pragma unroll
            for (int j = 0; j < 8; j++) u.gemm.Bs[lb_k + (j << 2)][lb_c] = rb[j];
            __syncthreads();

            if (s == 0) {                    // prefetch subtile 1
                int ks = kbase + 32;
#pragma unroll
                for (int i = 0; i < 4; i++)
                    ra[i] = x[(row0 + la_r + (i << 4)) * FF + ks + la_kk];
#pragma unroll
                for (int j = 0; j < 8; j++)
                    rb[j] = bok ? W[(ks + lb_k + (j << 2)) * NS + col0 + lb_c] : 0.f;
            }

#pragma unroll
            for (int kk = 0; kk < 32; kk++) {
                unsigned long long B0 = *reinterpret_cast<const unsigned long long*>(
                    &u.gemm.Bs[kk][tx << 1]);
                unsigned long long B1 = *reinterpret_cast<const unsigned long long*>(
                    &u.gemm.Bs[kk][(tx << 1) + 64]);
                unsigned long long A0 = dup_f32x2(u.gemm.As[kk][ty]);
                unsigned long long A1 = dup_f32x2(u.gemm.As[kk][ty + 16]);
                unsigned long long A2 = dup_f32x2(u.gemm.As[kk][ty + 32]);
                unsigned long long A3 = dup_f32x2(u.gemm.As[kk][ty + 48]);
                ffma2(acc[0][0], A0, B0); ffma2(acc[0][1], A0, B1);
                ffma2(acc[1][0], A1, B0); ffma2(acc[1][1], A1, B1);
                ffma2(acc[2][0], A2, B0); ffma2(acc[2][1], A2, B1);
                ffma2(acc[3][0], A3, B0); ffma2(acc[3][1], A3, B1);
            }
        }
        float* gp = g_part + kc * (BB * PCOL);
#pragma unroll
        for (int i = 0; i < 4; i++) {
            int r = row0 + ty + (i << 4);
#pragma unroll
            for (int j = 0; j < 2; j++) {
                int c = col0 + (tx << 1) + (j << 6);
                float2 v; *reinterpret_cast<unsigned long long*>(&v) = acc[i][j];
                if (c + 1 < NS) {
                    *reinterpret_cast<float2*>(&gp[r * PCOL + c]) = v;
                } else if (c < NS) {
                    gp[r * PCOL + c] = v.x;
                }
            }
        }
    }
    grid_sync();

    // ====== P2: q_node via LEVEL-ORDER recurrence (bit-identical to walk) ==
    {
        for (int idx = tid; idx < 4 * NS; idx += NTHR) {
            int j = idx / NS;
            int col = idx - j * NS;
            int b = (blockIdx.x << 2) + j;
            int o = b * PCOL + col;
            float s = 0.f;
#pragma unroll
            for (int ch = 0; ch < NKC; ch++) s += g_part[ch * (BB * PCOL) + o];
            u.p2.sq4[j][col] = s + bias[col];
        }
        if (tid < 4) {                       // root: empty ancestor set -> 1
            u.p2.sv[tid][0] = 1.0f;
            g_qnode[((blockIdx.x << 2) + tid) * NN + 0] = 1.0f;
        }
        __syncthreads();

#pragma unroll
        for (int d = 1; d <= 8; d++) {       // level d: nodes [2^d-1, 2^(d+1)-1)
            int start = (1 << d) - 1;
            int cnt = 1 << d;
            for (int idx = tid; idx < 4 * cnt; idx += NTHR) {
                int j = idx >> d;
                int off = idx & (cnt - 1);
                int n = start + off;
                int p = (n - 1) >> 1;        // p <= 254 < NS: valid split
                float s = u.p2.sq4[j][p];
                float v = fminf(u.p2.sv[j][p], (n & 1) ? -s : s);
                u.p2.sv[j][n] = v;
                g_qnode[((blockIdx.x << 2) + j) * NN + n] = v;
            }
            __syncthreads();
        }
    }
    grid_sync();

    // ====== P3: g_a + initial softmax; 4 nodes/block (256 active thr) ======
    {
        int nl = tid & 3;                    // node lane
        int bg = (tid >> 2) & 63;            // batch group 0..63
        bool act = tid < 256;
        int n = (blockIdx.x << 2) + nl;
        bool valid = act && (n < NN);

        float acc[NC];
#pragma unroll
        for (int c = 0; c < NC; c++) acc[c] = 0.f;

        if (act) {
#pragma unroll
            for (int it = 0; it < 8; it++) {
                int b = bg + (it << 6);
                float thr = valid ? (g_qnode[b * NN + n] + 0.5f) : 0.f;
#pragma unroll
                for (int c = 0; c < NC; c++) {
                    float a = 0.05f * (float)c;
                    float d = a - thr;
                    if (a <= thr) acc[c] += d * d;
                }
            }
#pragma unroll
            for (int c = 0; c < NC; c++) u.red[bg][nl * NC + c] = acc[c];
        }
        __syncthreads();

        if (tid < 4 * NC) {                  // 84 column sums (deterministic)
            float s = 0.f;
#pragma unroll
            for (int g2 = 0; g2 < 64; g2++) s += u.red[g2][tid];
            int nn2 = (blockIdx.x << 2) + tid / NC;
            int c = tid % NC;
            if (nn2 < NN) {
                float a = 0.05f * (float)c;
                g_ga[nn2 * NC + c] = 0.5f * a * a + 0.5f * s;
            }
            u.red[0][tid] = s;
        }
        __syncthreads();

        if (tid < 4) {                       // softmax init per node
            int n2 = (blockIdx.x << 2) + tid;
            if (n2 < NN) {
                const float* row = &u.red[0][tid * NC];
                float m = -FLT_MAX;
#pragma unroll
                for (int c = 0; c < NC; c++) {
                    float a = 0.05f * (float)c;
                    float g = 0.5f * a * a + 0.5f * row[c];
                    m = fmaxf(m, -TEMP * g);
                }
                float s = 0.f, w = 0.f;
#pragma unroll
                for (int c = 0; c < NC; c++) {
                    float a = 0.05f * (float)c;
                    float g = 0.5f * a * a + 0.5f * row[c];
                    float e = expf(-TEMP * g - m);
                    s += e; w += a * e;
                }
                g_agrpi[n2] = w / s;
            }
        }
    }
    grid_sync();

    // ====== P4: REDUNDANT scan — every block computes the identical merge
    // sequence locally (deterministic ops -> identical results). Removes the
    // done-counter / scan-flag / g_anode handshake entirely. ================
    {
        for (int i = tid; i < NN * NC; i += NTHR) u.s_ga[i] = g_ga[i];
        for (int i = tid; i < 512; i += NTHR) {
            s_cnt[i] = 0.f;
            s_agrp[i] = (i < NN) ? g_agrpi[i] : 0.f;
        }
        __syncthreads();
        // initial viol (permuted storage): anode = agrp (identity n2g)
        if (tid < NN)
            s_viol[VIDX(tid)] = s_agrp[tid] - ((tid == 0) ? 1.0f : s_agrp[(tid - 1) >> 1]);
        if (tid == NN) s_viol[VIDX(NN)] = -FLT_MAX;   // pad sentinel (slot 511)
        __syncthreads();

        if (tid < 32) {                      // warp 0 runs the loop alone
            int lane = tid;
            const unsigned FULL = 0xffffffffu;
            int  cl = (lane < NC) ? lane : (NC - 1);
            float ac = 0.05f * (float)cl;
            const float* sga = u.s_ga;
            const float4* vp = (const float4*)(s_viol + (lane << 4));

            for (int iter = 0; iter <= NN; ++iter) {
                // per-lane first-argmax over 16 contiguous (permuted) viols
                float4 q0 = vp[0], q1 = vp[1], q2 = vp[2], q3 = vp[3];
                float vv[16] = { q0.x, q0.y, q0.z, q0.w, q1.x, q1.y, q1.z, q1.w,
                                 q2.x, q2.y, q2.z, q2.w, q3.x, q3.y, q3.z, q3.w };
                float bv = vv[0]; int bk = 0;
#pragma unroll
                for (int k = 1; k < 16; k++)
                    if (vv[k] > bv) { bv = vv[k]; bk = k; }   // strict > = first idx
                int bidx = lane + (bk << 5);

                unsigned key  = ordk(bv);
                unsigned kmax = __reduce_max_sync(FULL, key);
                int t = __reduce_min_sync(FULL, (key == kmax) ? bidx : 1023);
                float vmax = iordk(kmax);

                if (!(vmax <= 1e-8f && t > 0 && iter < NN)) break;

                int p = (t - 1) >> 1;
                int sib = (t & 1) ? (t + 1) : (t - 1);
                int l1 = 2 * t + 1, r1 = 2 * t + 2;

                // all lanes read cnt[t] (broadcast LDS); store deferred to lane 0
                float cnew = s_cnt[t] + 1.0f;

                // dual softmax: groups t and p (same association order as before)
                float g1 = (1.0f - cnew) * sga[t * NC + cl];
                if (l1 < NN) g1 += s_cnt[l1] * sga[l1 * NC + cl];
                if (r1 < NN) g1 += s_cnt[r1] * sga[r1 * NC + cl];
                int l2 = 2 * p + 1, r2 = 2 * p + 2;     // == {t, sib}
                float cl2 = (l2 == t) ? cnew : s_cnt[l2];
                float cr2 = (r2 == t) ? cnew : s_cnt[r2];
                float g2v = (1.0f - s_cnt[p]) * sga[p * NC + cl]
                          + cl2 * sga[l2 * NC + cl]
                          + cr2 * sga[r2 * NC + cl];
                float z1 = -TEMP * g1, z2 = -TEMP * g2v;
                unsigned m1 = __reduce_max_sync(FULL, (lane < NC) ? ordk(z1) : 0u);
                unsigned m2 = __reduce_max_sync(FULL, (lane < NC) ? ordk(z2) : 0u);
                float e1 = (lane < NC) ? expf(z1 - iordk(m1)) : 0.f;
                float e2 = (lane < NC) ? expf(z2 - iordk(m2)) : 0.f;
                float s1 = e1, w1 = ac * e1, s2 = e2, w2 = ac * e2;
#pragma unroll
                for (int off = 16; off; off >>= 1) {
                    s1 += __shfl_xor_sync(FULL, s1, off);
                    w1 += __shfl_xor_sync(FULL, w1, off);
                    s2 += __shfl_xor_sync(FULL, s2, off);
                    w2 += __shfl_xor_sync(FULL, w2, off);
                }
                // butterfly leaves identical bits in ALL lanes -> register agrp
                float at  = w1 / s1;
                float ap_ = w2 / s2;
                if (lane == 0) { s_agrp[t] = at; s_agrp[p] = ap_; s_cnt[t] = cnew; }

                // viol patch from registers (reads of smem touch only UNCHANGED
                // entries; changed {t,p} agrp and cnt[t] substituted from regs)
                if (lane < 11) {
                    int i;
                    switch (lane) {
                        case 0:  i = t; break;
                        case 1:  i = p; break;
                        case 2:  i = sib; break;
                        case 3:  i = l1; break;
                        case 4:  i = r1; break;
                        case 5:  i = 2 * sib + 1; break;
                        case 6:  i = 2 * sib + 2; break;
                        case 7:  i = 2 * l1 + 1; break;
                        case 8:  i = 2 * l1 + 2; break;
                        case 9:  i = 2 * r1 + 1; break;
                        default: i = 2 * r1 + 2; break;
                    }
                    if (i < NN) {
                        auto agrp_of = [&](int xx) -> float {
                            return (xx == t) ? at : (xx == p) ? ap_ : s_agrp[xx];
                        };
                        auto anode_r = [&](int xx) -> float {
                            if (xx == 0) return agrp_of(0);
                            float fc = (xx == t) ? cnew : s_cnt[xx];
                            return fc * agrp_of((xx - 1) >> 1)
                                 + (1.0f - fc) * agrp_of(xx);
                        };
                        float an = anode_r(i);
                        float ap2 = (i == 0) ? 1.0f : anode_r((i - 1) >> 1);
                        s_viol[VIDX(i)] = an - ap2;
                    }
                }
                __syncwarp(FULL);
            }
        }
        __syncthreads();                     // scan state final for whole block
    }

    // ====== P5: trajectory = clip(q_node, 0, a_node); anode from local
    // (cnt, agrp) — same expression bits as the old g_anode writeback. ======
    {
        int b0 = blockIdx.x << 2;
        for (int n = tid; n < NN; n += NTHR) {     // single pass: NN < NTHR
            float an;
            if (n == 0) an = s_agrp[0];
            else {
                float fc = s_cnt[n];
                an = fc * s_agrp[(n - 1) >> 1] + (1.0f - fc) * s_agrp[n];
            }
#pragma unroll
            for (int j = 0; j < 4; j++) {
                int o = (b0 + j) * NN + n;
                out[o] = fminf(fmaxf(g_qnode[o], 0.0f), an);
            }
        }
    }
}

// ---------------------------------------------------------------------------
extern "C" void kernel_launch(void* const* d_in, const int* in_sizes, int n_in,
                              void* d_out, int out_size) {
    const float* x = (const float*)d_in[0];
    const float* W = (const float*)d_in[1];
    const float* b = (const float*)d_in[2];
    float* out = (float*)d_out;

    fused_kernel<<<GRID, NTHR>>>(x, W, b, out);
}